// round 2
// baseline (speedup 1.0000x reference)
#include <cuda_runtime.h>
#include <cstdint>

// Problem constants
// x: [16, 64, 128, 128]  (B, C, H, W), HX = HY = 64
// NSEQ = 2048 sequences per pass, T = 128 steps, hidden 64.

__device__ float g_pre[2048 * 128 * 64];   // pre-activations (reused by both passes)
__device__ float g_mid[2048 * 128 * 64];   // out_x, layout [b*128+h][w][j]
__device__ float g_WTx[64 * 64];           // Wih_x transposed: [c][j]
__device__ float g_WTy[64 * 64];           // Wih_y transposed: [j][j2]
__device__ float g_bsx[64];                // bih_x + bhh_x
__device__ float g_bsy[64];                // bih_y + bhh_y

using ull = unsigned long long;

__device__ __forceinline__ ull ffma2(ull a, ull b, ull c) {
    ull d;
    asm("fma.rn.f32x2 %0, %1, %2, %3;" : "=l"(d) : "l"(a), "l"(b), "l"(c));
    return d;
}
__device__ __forceinline__ ull dup2(float x) {
    unsigned u = __float_as_uint(x);
    return ((ull)u << 32) | (ull)u;
}
__device__ __forceinline__ float lo_f(ull v) { return __uint_as_float((unsigned)(v & 0xffffffffull)); }
__device__ __forceinline__ float hi_f(ull v) { return __uint_as_float((unsigned)(v >> 32)); }
__device__ __forceinline__ float tanh_fast(float x) {
    float r;
    asm("tanh.approx.f32 %0, %1;" : "=f"(r) : "f"(x));
    return r;
}

// ---------------------------------------------------------------------------
// Prep: transpose Wih matrices, sum biases. One tiny block.
// ---------------------------------------------------------------------------
__global__ void prep_kernel(const float* __restrict__ Wih_x,
                            const float* __restrict__ Wih_y,
                            const float* __restrict__ bih_x,
                            const float* __restrict__ bhh_x,
                            const float* __restrict__ bih_y,
                            const float* __restrict__ bhh_y) {
    int t = threadIdx.x;
    for (int e = t; e < 4096; e += 256) {
        int j = e >> 6, c = e & 63;
        g_WTx[c * 64 + j] = Wih_x[j * 64 + c];
        g_WTy[c * 64 + j] = Wih_y[j * 64 + c];
    }
    if (t < 64) {
        g_bsx[t] = bih_x[t] + bhh_x[t];
        g_bsy[t] = bih_y[t] + bhh_y[t];
    }
}

// ---------------------------------------------------------------------------
// Projection GEMM: out[row][pos][j] = bias[j] + sum_c in[c][pos] * W[j][c]
// MODE 0 (x-pass): row = b*128+h, pos = w (64 per block), in = x (strided gather)
// MODE 1 (y-pass): row = b*128+w, pos = h (64 per block), in = g_mid (transposed)
// Grid: 4096 blocks (row * 2 halves), 256 threads.
// ---------------------------------------------------------------------------
template <int MODE>
__global__ __launch_bounds__(256) void proj_kernel(const float* __restrict__ src) {
    __shared__ float in_sh[64][68];   // [reduction c][position]
    __shared__ float Wsh[64][68];     // [reduction c][output j]

    int tid  = threadIdx.x;
    int blk  = blockIdx.x;
    int half = blk & 1;
    int row  = blk >> 1;              // 0..2047

    if (MODE == 0) {
        int b = row >> 7, h = row & 127, w0 = half * 64;
        const float* xb = src + (size_t)b * 64 * 16384 + h * 128 + w0;
        #pragma unroll
        for (int e = tid; e < 4096; e += 256) {
            int c = e >> 6, wl = e & 63;
            in_sh[c][wl] = xb[c * 16384 + wl];
        }
    } else {
        int b = row >> 7, w = row & 127, h0 = half * 64;
        const float* mb = g_mid + (size_t)(b * 128 + h0) * 8192 + w * 64;
        #pragma unroll
        for (int e = tid; e < 4096; e += 256) {
            int hl = e >> 6, jj = e & 63;
            in_sh[jj][hl] = mb[hl * 8192 + jj];   // transpose into reduction-major
        }
    }
    {
        const float* WT = (MODE == 0) ? g_WTx : g_WTy;
        #pragma unroll
        for (int e = tid; e < 4096; e += 256) {
            int c = e >> 6, j = e & 63;
            Wsh[c][j] = WT[e];
        }
    }
    __syncthreads();

    int pt = tid & 15;   // 16 position-groups of 4
    int jt = tid >> 4;   // 16 output-groups of 4

    const float* bs = (MODE == 0) ? g_bsx : g_bsy;
    float4 b4 = *(const float4*)&bs[jt * 4];
    ull a00 = dup2(b4.x), a01 = dup2(b4.y), a02 = dup2(b4.z), a03 = dup2(b4.w);
    ull a10 = a00, a11 = a01, a12 = a02, a13 = a03;

    #pragma unroll
    for (int c = 0; c < 64; c++) {
        ulonglong2 xv = *(const ulonglong2*)&in_sh[c][pt * 4];
        float4 wv = *(const float4*)&Wsh[c][jt * 4];
        ull w0 = dup2(wv.x), w1 = dup2(wv.y), w2 = dup2(wv.z), w3 = dup2(wv.w);
        a00 = ffma2(xv.x, w0, a00);  a10 = ffma2(xv.y, w0, a10);
        a01 = ffma2(xv.x, w1, a01);  a11 = ffma2(xv.y, w1, a11);
        a02 = ffma2(xv.x, w2, a02);  a12 = ffma2(xv.y, w2, a12);
        a03 = ffma2(xv.x, w3, a03);  a13 = ffma2(xv.y, w3, a13);
    }

    float* dst = g_pre + (size_t)row * 8192 + (half * 64 + pt * 4) * 64 + jt * 4;
    float4 o;
    o = make_float4(lo_f(a00), lo_f(a01), lo_f(a02), lo_f(a03)); *(float4*)(dst + 0 * 64) = o;
    o = make_float4(hi_f(a00), hi_f(a01), hi_f(a02), hi_f(a03)); *(float4*)(dst + 1 * 64) = o;
    o = make_float4(lo_f(a10), lo_f(a11), lo_f(a12), lo_f(a13)); *(float4*)(dst + 2 * 64) = o;
    o = make_float4(hi_f(a10), hi_f(a11), hi_f(a12), hi_f(a13)); *(float4*)(dst + 3 * 64) = o;
}

// ---------------------------------------------------------------------------
// Recurrent scan: h_t = tanh(pre_t + Whh @ h_{t-1}); 4 sequences per block.
// MODE 0: write g_mid[seq][t][j] (coalesced).
// MODE 1: write final output out[b][j][t][w] via shared-memory remap.
// Grid: 512 blocks, 256 threads (seq-lane sl = tid/64, hidden j = tid%64).
// ---------------------------------------------------------------------------
template <int MODE>
__global__ __launch_bounds__(256) void scan_kernel(const float* __restrict__ Whh,
                                                   float* __restrict__ out) {
    __shared__ float hbuf[2][4][72];   // pad 72: conflict-free remap reads

    int tid = threadIdx.x;
    int sl  = tid >> 6;
    int j   = tid & 63;
    int seq = blockIdx.x * 4 + sl;

    const float* pre = g_pre + (size_t)seq * 8192 + j;

    // Whh row j packed as 32 f32x2 registers
    ull w2[32];
    const ull* wr = (const ull*)(Whh + j * 64);
    #pragma unroll
    for (int i = 0; i < 32; i++) w2[i] = wr[i];

    hbuf[0][sl][j] = 0.f;
    __syncthreads();

    float* midp = g_mid + (size_t)seq * 8192 + j;
    float* outp = nullptr;
    int j2 = 0, sw = 0;
    if (MODE == 1) {
        int s0 = blockIdx.x * 4;
        int b  = s0 >> 7;
        int w0 = s0 & 127;
        j2 = tid >> 2;           // 0..63 output channel
        sw = tid & 3;            // 0..3  w within block
        outp = out + (size_t)b * 1048576 + (size_t)j2 * 16384 + w0 + sw;
    }

    float pv = pre[0];
    int cur = 0;
    for (int t = 0; t < 128; t++) {
        float pvn = 0.f;
        if (t < 127) pvn = pre[(t + 1) * 64];   // prefetch next step

        const ulonglong2* h2 = (const ulonglong2*)hbuf[cur][sl];
        ull a0 = 0, a1 = 0, a2 = 0, a3 = 0;
        #pragma unroll
        for (int i = 0; i < 16; i += 2) {
            ulonglong2 ha = h2[i];
            a0 = ffma2(w2[2 * i],     ha.x, a0);
            a1 = ffma2(w2[2 * i + 1], ha.y, a1);
            ulonglong2 hb = h2[i + 1];
            a2 = ffma2(w2[2 * i + 2], hb.x, a2);
            a3 = ffma2(w2[2 * i + 3], hb.y, a3);
        }
        float s = pv + lo_f(a0) + hi_f(a0) + lo_f(a1) + hi_f(a1)
                     + lo_f(a2) + hi_f(a2) + lo_f(a3) + hi_f(a3);
        float hn = tanh_fast(s);

        hbuf[cur ^ 1][sl][j] = hn;
        __syncthreads();

        if (MODE == 0) {
            midp[t * 64] = hn;                       // [seq][t][j], coalesced
        } else {
            float v = hbuf[cur ^ 1][sw][j2];         // conflict-free remap
            outp[t * 128] = v;                       // out[b][j2][t][w0+sw]
        }

        cur ^= 1;
        pv = pvn;
    }
}

// ---------------------------------------------------------------------------
extern "C" void kernel_launch(void* const* d_in, const int* in_sizes, int n_in,
                              void* d_out, int out_size) {
    const float* x     = (const float*)d_in[0];
    const float* Wih_x = (const float*)d_in[1];
    const float* Whh_x = (const float*)d_in[2];
    const float* bih_x = (const float*)d_in[3];
    const float* bhh_x = (const float*)d_in[4];
    const float* Wih_y = (const float*)d_in[5];
    const float* Whh_y = (const float*)d_in[6];
    const float* bih_y = (const float*)d_in[7];
    const float* bhh_y = (const float*)d_in[8];
    float* out = (float*)d_out;

    prep_kernel<<<1, 256>>>(Wih_x, Wih_y, bih_x, bhh_x, bih_y, bhh_y);
    proj_kernel<0><<<4096, 256>>>(x);            // pre_x into g_pre
    scan_kernel<0><<<512, 256>>>(Whh_x, nullptr);// scan along W -> g_mid
    proj_kernel<1><<<4096, 256>>>(nullptr);      // pre_y into g_pre (reuse)
    scan_kernel<1><<<512, 256>>>(Whh_y, out);    // scan along H -> transposed out
}

// round 3
// speedup vs baseline: 1.1499x; 1.1499x over previous
#include <cuda_runtime.h>
#include <cstdint>

// x: [16, 64, 128, 128] (B, C, H, W), HX = HY = 64.
// Pass 1: 2048 sequences (b,h) of length 128 (along w).
// Pass 2: 2048 sequences (b,w) of length 128 (along h).

using ull = unsigned long long;

__device__ float g_pre[2048 * 128 * 64];   // [seq][t][j]
__device__ float g_mid[2048 * 128 * 64];   // [b][w][j][h]  (out_x, transposed for y-pass)
__device__ ull   g_Wdx[64 * 64];           // dup'd Wih_x^T: [c][j] -> (w,w)
__device__ ull   g_Wdy[64 * 64];           // dup'd Wih_y^T
__device__ ull   g_bsdx[64];               // dup'd bias sum x
__device__ ull   g_bsdy[64];               // dup'd bias sum y

__device__ __forceinline__ ull ffma2(ull a, ull b, ull c) {
    ull d;
    asm("fma.rn.f32x2 %0, %1, %2, %3;" : "=l"(d) : "l"(a), "l"(b), "l"(c));
    return d;
}
__device__ __forceinline__ ull addf2(ull a, ull b) {
    ull d;
    asm("add.rn.f32x2 %0, %1, %2;" : "=l"(d) : "l"(a), "l"(b));
    return d;
}
__device__ __forceinline__ ull dup2(float x) {
    unsigned u = __float_as_uint(x);
    return ((ull)u << 32) | (ull)u;
}
__device__ __forceinline__ float lo_f(ull v) { return __uint_as_float((unsigned)(v & 0xffffffffull)); }
__device__ __forceinline__ float hi_f(ull v) { return __uint_as_float((unsigned)(v >> 32)); }
__device__ __forceinline__ float tanh_fast(float x) {
    float r;
    asm("tanh.approx.f32 %0, %1;" : "=f"(r) : "f"(x));
    return r;
}
__device__ __forceinline__ void cp_async16(uint32_t dst, const void* src) {
    asm volatile("cp.async.cg.shared.global [%0], [%1], 16;" :: "r"(dst), "l"(src));
}
#define CP_COMMIT() asm volatile("cp.async.commit_group;")
#define CP_WAIT(n)  asm volatile("cp.async.wait_group %0;" :: "n"(n))

// ---------------------------------------------------------------------------
// Prep: duplicated-weight tables + dup'd bias sums. One tiny block.
// ---------------------------------------------------------------------------
__global__ void prep_kernel(const float* __restrict__ Wih_x,
                            const float* __restrict__ Wih_y,
                            const float* __restrict__ bih_x,
                            const float* __restrict__ bhh_x,
                            const float* __restrict__ bih_y,
                            const float* __restrict__ bhh_y) {
    int t = threadIdx.x;
    for (int e = t; e < 4096; e += 256) {
        int c = e >> 6, j = e & 63;
        g_Wdx[c * 64 + j] = dup2(Wih_x[j * 64 + c]);
        g_Wdy[c * 64 + j] = dup2(Wih_y[j * 64 + c]);
    }
    if (t < 64) {
        g_bsdx[t] = dup2(bih_x[t] + bhh_x[t]);
        g_bsdy[t] = dup2(bih_y[t] + bhh_y[t]);
    }
}

// ---------------------------------------------------------------------------
// Projection: pre[row][pos][j] = bias[j] + sum_c in[c][pos] * W[j][c]
// MODE 0: row=(b,h), pos=w 0..127, in = x[b][c][h][w]        (stride_c = 16384)
// MODE 1: row=(b,w), pos=h 0..127, in = g_mid[b][w][c][h]    (stride_c = 128)
// Grid 2048 (one block per row), 256 threads.
// Thread tile: 4 positions (FFMA2-paired) x 8 outputs.
// ---------------------------------------------------------------------------
template <int MODE>
__global__ __launch_bounds__(256, 3) void proj_kernel(const float* __restrict__ src) {
    __shared__ float in_sh[64][132];   // [c][pos], pad 132 keeps 16B-aligned rows

    int tid = threadIdx.x;
    int row = blockIdx.x;

    const float* base;
    size_t stride_c;
    if (MODE == 0) {
        int b = row >> 7, h = row & 127;
        base = src + (size_t)b * 1048576 + (size_t)h * 128;
        stride_c = 16384;
    } else {
        base = g_mid + (size_t)row * 8192;
        stride_c = 128;
    }

    // Stage 64 x 128 input tile via cp.async (each thread: 8 x 16B)
    {
        int c0 = tid >> 5, w4 = tid & 31;
        uint32_t shb = (uint32_t)__cvta_generic_to_shared(&in_sh[0][0]);
        #pragma unroll
        for (int i = 0; i < 8; i++) {
            int c = c0 + i * 8;
            uint32_t d = shb + (c * 132 + w4 * 4) * 4;
            cp_async16(d, base + (size_t)c * stride_c + w4 * 4);
        }
        CP_COMMIT();
        CP_WAIT(0);
        __syncthreads();
    }

    int pt = tid & 31;   // position group of 4
    int jt = tid >> 5;   // output group of 8 (uniform within warp)

    const ull* Wd = ((MODE == 0) ? g_Wdx : g_Wdy) + jt * 8;
    const ull* bd = ((MODE == 0) ? g_bsdx : g_bsdy) + jt * 8;

    ull a0[8], a1[8];
    #pragma unroll
    for (int o = 0; o < 8; o++) { ull bv = bd[o]; a0[o] = bv; a1[o] = bv; }

    #pragma unroll 16
    for (int c = 0; c < 64; c++) {
        ulonglong2 xv = *(const ulonglong2*)&in_sh[c][pt * 4];
        const ulonglong2* wp = (const ulonglong2*)&Wd[c * 64];
        ulonglong2 wA = wp[0], wB = wp[1], wC = wp[2], wD = wp[3];
        a0[0] = ffma2(xv.x, wA.x, a0[0]);  a1[0] = ffma2(xv.y, wA.x, a1[0]);
        a0[1] = ffma2(xv.x, wA.y, a0[1]);  a1[1] = ffma2(xv.y, wA.y, a1[1]);
        a0[2] = ffma2(xv.x, wB.x, a0[2]);  a1[2] = ffma2(xv.y, wB.x, a1[2]);
        a0[3] = ffma2(xv.x, wB.y, a0[3]);  a1[3] = ffma2(xv.y, wB.y, a1[3]);
        a0[4] = ffma2(xv.x, wC.x, a0[4]);  a1[4] = ffma2(xv.y, wC.x, a1[4]);
        a0[5] = ffma2(xv.x, wC.y, a0[5]);  a1[5] = ffma2(xv.y, wC.y, a1[5]);
        a0[6] = ffma2(xv.x, wD.x, a0[6]);  a1[6] = ffma2(xv.y, wD.x, a1[6]);
        a0[7] = ffma2(xv.x, wD.y, a0[7]);  a1[7] = ffma2(xv.y, wD.y, a1[7]);
    }

    float* dst = g_pre + (size_t)row * 8192 + (pt * 4) * 64 + jt * 8;
    float4 o;
    o = make_float4(lo_f(a0[0]), lo_f(a0[1]), lo_f(a0[2]), lo_f(a0[3])); *(float4*)(dst + 0 * 64 + 0) = o;
    o = make_float4(lo_f(a0[4]), lo_f(a0[5]), lo_f(a0[6]), lo_f(a0[7])); *(float4*)(dst + 0 * 64 + 4) = o;
    o = make_float4(hi_f(a0[0]), hi_f(a0[1]), hi_f(a0[2]), hi_f(a0[3])); *(float4*)(dst + 1 * 64 + 0) = o;
    o = make_float4(hi_f(a0[4]), hi_f(a0[5]), hi_f(a0[6]), hi_f(a0[7])); *(float4*)(dst + 1 * 64 + 4) = o;
    o = make_float4(lo_f(a1[0]), lo_f(a1[1]), lo_f(a1[2]), lo_f(a1[3])); *(float4*)(dst + 2 * 64 + 0) = o;
    o = make_float4(lo_f(a1[4]), lo_f(a1[5]), lo_f(a1[6]), lo_f(a1[7])); *(float4*)(dst + 2 * 64 + 4) = o;
    o = make_float4(hi_f(a1[0]), hi_f(a1[1]), hi_f(a1[2]), hi_f(a1[3])); *(float4*)(dst + 3 * 64 + 0) = o;
    o = make_float4(hi_f(a1[4]), hi_f(a1[5]), hi_f(a1[6]), hi_f(a1[7])); *(float4*)(dst + 3 * 64 + 4) = o;
}

// ---------------------------------------------------------------------------
// Recurrent scan: h_t = tanh(pre_t + Whh @ h_{t-1}), 4 sequences per block,
// pre staged in shared via double-buffered cp.async chunks of 16 steps.
// MODE 0: write g_mid[b][t][j][h] (16B store groups via shared remap)
// MODE 1: write out[b][j][t][w]   (16B store groups via shared remap)
// Grid 512, block 256 (sl = tid/64 sequence lane, j = tid%64 hidden unit).
// ---------------------------------------------------------------------------
template <int MODE>
__global__ __launch_bounds__(256, 2) void scan_kernel(const float* __restrict__ Whh,
                                                      float* __restrict__ out) {
    __shared__ float pre_sh[2][4][16][64];   // [buf][sl][tt][j]
    __shared__ float hbuf[2][4][72];

    int tid = threadIdx.x;
    int sl  = tid >> 6;
    int j   = tid & 63;
    int s0  = blockIdx.x * 4;
    int b   = s0 >> 7;
    int p0  = s0 & 127;                      // h0 (MODE0) or w0 (MODE1)

    const float* preg = g_pre + (size_t)s0 * 8192;

    // Whh row j as 32 packed f32x2 registers
    ull w2[32];
    {
        const ull* wr = (const ull*)(Whh + j * 64);
        #pragma unroll
        for (int i = 0; i < 32; i++) w2[i] = wr[i];
    }

    hbuf[0][sl][j] = 0.f;

    uint32_t preb = (uint32_t)__cvta_generic_to_shared(&pre_sh[0][0][0][0]);

    // chunk 0
    {
        #pragma unroll
        for (int s = 0; s < 4; s++) {
            uint32_t d = preb + (s * 1024 + tid * 4) * 4;
            cp_async16(d, preg + (size_t)s * 8192 + tid * 4);
        }
        CP_COMMIT();
    }

    int j2 = tid >> 2;        // remap: output channel
    int s2 = tid & 3;         // remap: sequence within block
    float* outp;
    if (MODE == 0) {
        outp = g_mid + (size_t)b * 1048576 + (size_t)j2 * 128 + p0 + s2;   // + t*8192
    } else {
        outp = out + (size_t)b * 1048576 + (size_t)j2 * 16384 + p0 + s2;   // + t*128
    }

    int cur = 0;
    for (int k = 0; k < 8; k++) {
        __syncthreads();                       // all done reading buf[(k+1)&1] (chunk k-1)
        if (k < 7) {
            int bk = (k + 1) & 1;
            #pragma unroll
            for (int s = 0; s < 4; s++) {
                uint32_t d = preb + ((bk * 4 + s) * 1024 + tid * 4) * 4;
                cp_async16(d, preg + (size_t)s * 8192 + (k + 1) * 1024 + tid * 4);
            }
            CP_COMMIT();
            CP_WAIT(1);                        // chunk k landed (k+1 in flight)
        } else {
            CP_WAIT(0);
        }
        __syncthreads();                       // chunk k visible block-wide

        const float* pvp = &pre_sh[k & 1][sl][0][j];

        #pragma unroll 4
        for (int tt = 0; tt < 16; tt++) {
            float pv = pvp[tt * 64];

            const ulonglong2* h2 = (const ulonglong2*)hbuf[cur][sl];
            ull a0 = 0, a1 = 0, a2 = 0, a3 = 0;
            #pragma unroll
            for (int i = 0; i < 16; i += 2) {
                ulonglong2 ha = h2[i];
                a0 = ffma2(w2[2 * i],     ha.x, a0);
                a1 = ffma2(w2[2 * i + 1], ha.y, a1);
                ulonglong2 hb = h2[i + 1];
                a2 = ffma2(w2[2 * i + 2], hb.x, a2);
                a3 = ffma2(w2[2 * i + 3], hb.y, a3);
            }
            a0 = addf2(a0, a1);
            a2 = addf2(a2, a3);
            a0 = addf2(a0, a2);
            float s_ = pv + lo_f(a0) + hi_f(a0);
            float hn = tanh_fast(s_);

            int nxt = cur ^ 1;
            hbuf[nxt][sl][j] = hn;
            __syncthreads();

            float v = hbuf[nxt][s2][j2];       // conflict-free remap read
            int t = k * 16 + tt;
            if (MODE == 0) outp[(size_t)t * 8192] = v;
            else           outp[(size_t)t * 128]  = v;

            cur = nxt;
        }
    }
}

// ---------------------------------------------------------------------------
extern "C" void kernel_launch(void* const* d_in, const int* in_sizes, int n_in,
                              void* d_out, int out_size) {
    const float* x     = (const float*)d_in[0];
    const float* Wih_x = (const float*)d_in[1];
    const float* Whh_x = (const float*)d_in[2];
    const float* bih_x = (const float*)d_in[3];
    const float* bhh_x = (const float*)d_in[4];
    const float* Wih_y = (const float*)d_in[5];
    const float* Whh_y = (const float*)d_in[6];
    const float* bih_y = (const float*)d_in[7];
    const float* bhh_y = (const float*)d_in[8];
    float* out = (float*)d_out;

    prep_kernel<<<1, 256>>>(Wih_x, Wih_y, bih_x, bhh_x, bih_y, bhh_y);
    proj_kernel<0><<<2048, 256>>>(x);                 // pre_x
    scan_kernel<0><<<512, 256>>>(Whh_x, nullptr);     // scan along w -> g_mid [b][w][j][h]
    proj_kernel<1><<<2048, 256>>>(nullptr);           // pre_y
    scan_kernel<1><<<512, 256>>>(Whh_y, out);         // scan along h -> out [b][j][h][w]
}

// round 5
// speedup vs baseline: 1.2939x; 1.1252x over previous
#include <cuda_runtime.h>
#include <cstdint>

// x: [16, 64, 128, 128] (B, C, H, W), HX = HY = 64.
// Pass 1: 2048 sequences (b,h), T=128 along w.
// Pass 2: 2048 sequences (b,w), T=128 along h.

using ull = unsigned long long;

__device__ float g_pre[2048 * 128 * 64];   // [seq][t][j]
__device__ float g_mid[2048 * 128 * 64];   // [b][w][j][h]
__device__ ull   g_Wdx[64 * 64];           // dup'd Wih_x^T: [c][j] -> (w,w)
__device__ ull   g_Wdy[64 * 64];
__device__ ull   g_bsdx[64];               // dup'd bias sums
__device__ ull   g_bsdy[64];

__device__ __forceinline__ ull ffma2(ull a, ull b, ull c) {
    ull d;
    asm("fma.rn.f32x2 %0, %1, %2, %3;" : "=l"(d) : "l"(a), "l"(b), "l"(c));
    return d;
}
__device__ __forceinline__ ull addf2(ull a, ull b) {
    ull d;
    asm("add.rn.f32x2 %0, %1, %2;" : "=l"(d) : "l"(a), "l"(b));
    return d;
}
__device__ __forceinline__ ull dup2(float x) {
    unsigned u = __float_as_uint(x);
    return ((ull)u << 32) | (ull)u;
}
__device__ __forceinline__ float lo_f(ull v) { return __uint_as_float((unsigned)(v & 0xffffffffull)); }
__device__ __forceinline__ float hi_f(ull v) { return __uint_as_float((unsigned)(v >> 32)); }
__device__ __forceinline__ float tanh_fast(float x) {
    float r;
    asm("tanh.approx.f32 %0, %1;" : "=f"(r) : "f"(x));
    return r;
}
__device__ __forceinline__ void cp_async16(uint32_t dst, const void* src) {
    asm volatile("cp.async.cg.shared.global [%0], [%1], 16;" :: "r"(dst), "l"(src));
}
#define CP_COMMIT() asm volatile("cp.async.commit_group;")
#define CP_WAIT(n)  asm volatile("cp.async.wait_group %0;" :: "n"(n))

// ---------------------------------------------------------------------------
// Prep: dup'd transposed weight tables + dup'd bias sums.
// ---------------------------------------------------------------------------
__global__ void prep_kernel(const float* __restrict__ Wih_x,
                            const float* __restrict__ Wih_y,
                            const float* __restrict__ bih_x,
                            const float* __restrict__ bhh_x,
                            const float* __restrict__ bih_y,
                            const float* __restrict__ bhh_y) {
    int t = threadIdx.x;
    for (int e = t; e < 4096; e += 256) {
        int c = e >> 6, j = e & 63;
        g_Wdx[c * 64 + j] = dup2(Wih_x[j * 64 + c]);
        g_Wdy[c * 64 + j] = dup2(Wih_y[j * 64 + c]);
    }
    if (t < 64) {
        g_bsdx[t] = dup2(bih_x[t] + bhh_x[t]);
        g_bsdy[t] = dup2(bih_y[t] + bhh_y[t]);
    }
}

// ---------------------------------------------------------------------------
// Projection: pre[row][pos][j] = bias[j] + sum_c in[c][pos] * W[j][c]
// Grid 2048 (one block per row of 128 positions, two 64-pos halves).
// Smem: dup'd W (32KB) + natural input half-tile (16KB) = 48KB.
// Thread tile: 4 positions (f32x2-paired) x 4 outputs -> 8 FFMA2 per c.
// ---------------------------------------------------------------------------
template <int MODE>
__global__ __launch_bounds__(256, 4) void proj_kernel(const float* __restrict__ src) {
    __shared__ float in_sh[64][64];    // [c][pos-half]  16KB
    __shared__ ull   Wd_sh[64][64];    // [c][j] dup'd   32KB

    int tid = threadIdx.x;
    int row = blockIdx.x;

    const float* base;
    size_t stride_c;
    if (MODE == 0) {
        int b = row >> 7, h = row & 127;
        base = src + (size_t)b * 1048576 + (size_t)h * 128;
        stride_c = 16384;
    } else {
        base = g_mid + (size_t)row * 8192;
        stride_c = 128;
    }

    uint32_t shW = (uint32_t)__cvta_generic_to_shared(&Wd_sh[0][0]);
    uint32_t shI = (uint32_t)__cvta_generic_to_shared(&in_sh[0][0]);

    // Stage dup'd W (once) + input half 0
    {
        const ull* Wg = (MODE == 0) ? g_Wdx : g_Wdy;
        #pragma unroll
        for (int i = 0; i < 8; i++) {
            int idx = tid * 2 + i * 512;          // ull units, 16B granules
            cp_async16(shW + idx * 8, Wg + idx);
        }
        #pragma unroll
        for (int i = 0; i < 4; i++) {
            int e = tid + i * 256;                // 0..1023 16B-granules
            int c = e >> 4, w4 = e & 15;
            cp_async16(shI + (c * 64 + w4 * 4) * 4,
                       base + (size_t)c * stride_c + w4 * 4);
        }
        CP_COMMIT();
        CP_WAIT(0);
        __syncthreads();
    }

    int pt = tid & 15;    // position group of 4
    int jt = tid >> 4;    // output group of 4 (uniform per half-warp)

    const ull* bd = ((MODE == 0) ? g_bsdx : g_bsdy) + jt * 4;
    ull b0 = bd[0], b1 = bd[1], b2 = bd[2], b3 = bd[3];

    #pragma unroll
    for (int half = 0; half < 2; half++) {
        ull a00 = b0, a01 = b1, a02 = b2, a03 = b3;   // pos pair 0 (p0,p1)
        ull a10 = b0, a11 = b1, a12 = b2, a13 = b3;   // pos pair 1 (p2,p3)

        #pragma unroll 16
        for (int c = 0; c < 64; c++) {
            ulonglong2 xv = *(const ulonglong2*)&in_sh[c][pt * 4];
            const ulonglong2* wq = (const ulonglong2*)&Wd_sh[c][jt * 4];
            ulonglong2 wA = wq[0], wB = wq[1];
            a00 = ffma2(xv.x, wA.x, a00);  a10 = ffma2(xv.y, wA.x, a10);
            a01 = ffma2(xv.x, wA.y, a01);  a11 = ffma2(xv.y, wA.y, a11);
            a02 = ffma2(xv.x, wB.x, a02);  a12 = ffma2(xv.y, wB.x, a12);
            a03 = ffma2(xv.x, wB.y, a03);  a13 = ffma2(xv.y, wB.y, a13);
        }

        // Restage half 1 while results are written out
        __syncthreads();
        if (half == 0) {
            #pragma unroll
            for (int i = 0; i < 4; i++) {
                int e = tid + i * 256;
                int c = e >> 4, w4 = e & 15;
                cp_async16(shI + (c * 64 + w4 * 4) * 4,
                           base + (size_t)c * stride_c + 64 + w4 * 4);
            }
            CP_COMMIT();
        }

        float* dst = g_pre + (size_t)row * 8192 + (half * 64 + pt * 4) * 64 + jt * 4;
        float4 o;
        o = make_float4(lo_f(a00), lo_f(a01), lo_f(a02), lo_f(a03)); *(float4*)(dst + 0 * 64) = o;
        o = make_float4(hi_f(a00), hi_f(a01), hi_f(a02), hi_f(a03)); *(float4*)(dst + 1 * 64) = o;
        o = make_float4(lo_f(a10), lo_f(a11), lo_f(a12), lo_f(a13)); *(float4*)(dst + 2 * 64) = o;
        o = make_float4(hi_f(a10), hi_f(a11), hi_f(a12), hi_f(a13)); *(float4*)(dst + 3 * 64) = o;

        if (half == 0) {
            CP_WAIT(0);
            __syncthreads();
        }
    }
}

// ---------------------------------------------------------------------------
// Recurrent scan: h_t = tanh(pre_t + Whh @ h_{t-1}); 2 sequences per block,
// 128 threads, pre staged via double-buffered cp.async chunks of 16 steps.
// MODE 0: write g_mid[b][w][j][h];  MODE 1: write out[b][j][h][w].
// ---------------------------------------------------------------------------
template <int MODE>
__global__ __launch_bounds__(128, 4) void scan_kernel(const float* __restrict__ Whh,
                                                      float* __restrict__ out) {
    __shared__ float pre_sh[2][2][16][64];   // [buf][sl][tt][j] 16KB
    __shared__ float hbuf[2][2][80];         // pad 80: conflict-free remap

    int tid = threadIdx.x;
    int sl  = tid >> 6;
    int j   = tid & 63;
    int s0  = blockIdx.x * 2;
    int b   = s0 >> 7;
    int p0  = s0 & 127;

    const float* preg = g_pre + (size_t)s0 * 8192;

    ull w2[32];
    {
        const ull* wr = (const ull*)(Whh + j * 64);
        #pragma unroll
        for (int i = 0; i < 32; i++) w2[i] = wr[i];
    }

    hbuf[0][sl][j] = 0.f;

    uint32_t preb = (uint32_t)__cvta_generic_to_shared(&pre_sh[0][0][0][0]);

    // chunk 0: 2048 floats (2 seqs x 16 steps x 64)
    {
        #pragma unroll
        for (int i = 0; i < 4; i++) {
            int e = tid * 4 + i * 512;
            int seq = e >> 10, off = e & 1023;
            cp_async16(preb + e * 4, preg + (size_t)seq * 8192 + off);
        }
        CP_COMMIT();
    }

    int j2 = tid >> 1;        // remap: output channel
    int s2 = tid & 1;         // remap: sequence within block
    float* outp;
    if (MODE == 0) {
        outp = g_mid + (size_t)b * 1048576 + (size_t)j2 * 128 + p0 + s2;   // + t*8192
    } else {
        outp = out + (size_t)b * 1048576 + (size_t)j2 * 16384 + p0 + s2;   // + t*128
    }

    int cur = 0;
    for (int k = 0; k < 8; k++) {
        __syncthreads();                       // buf (k+1)&1 free to overwrite
        if (k < 7) {
            int bk = (k + 1) & 1;
            #pragma unroll
            for (int i = 0; i < 4; i++) {
                int e = tid * 4 + i * 512;
                int seq = e >> 10, off = e & 1023;
                cp_async16(preb + (bk * 2048 + e) * 4,
                           preg + (size_t)seq * 8192 + (k + 1) * 1024 + off);
            }
            CP_COMMIT();
            CP_WAIT(1);                        // chunk k landed
        } else {
            CP_WAIT(0);
        }
        __syncthreads();

        const float* pvp = &pre_sh[k & 1][sl][0][j];

        #pragma unroll 4
        for (int tt = 0; tt < 16; tt++) {
            float pv = pvp[tt * 64];

            const ulonglong2* h2 = (const ulonglong2*)hbuf[cur][sl];
            ull a0 = 0, a1 = 0, a2 = 0, a3 = 0;
            #pragma unroll
            for (int i = 0; i < 16; i += 2) {
                ulonglong2 ha = h2[i];
                a0 = ffma2(w2[2 * i],     ha.x, a0);
                a1 = ffma2(w2[2 * i + 1], ha.y, a1);
                ulonglong2 hb = h2[i + 1];
                a2 = ffma2(w2[2 * i + 2], hb.x, a2);
                a3 = ffma2(w2[2 * i + 3], hb.y, a3);
            }
            a0 = addf2(a0, a1);
            a2 = addf2(a2, a3);
            a0 = addf2(a0, a2);
            float s_ = pv + lo_f(a0) + hi_f(a0);
            float hn = tanh_fast(s_);

            int nxt = cur ^ 1;
            hbuf[nxt][sl][j] = hn;
            __syncthreads();

            float v = hbuf[nxt][s2][j2];       // conflict-free remap read
            int t = k * 16 + tt;
            if (MODE == 0) outp[(size_t)t * 8192] = v;
            else           outp[(size_t)t * 128]  = v;

            cur = nxt;
        }
    }
}

// ---------------------------------------------------------------------------
extern "C" void kernel_launch(void* const* d_in, const int* in_sizes, int n_in,
                              void* d_out, int out_size) {
    const float* x     = (const float*)d_in[0];
    const float* Wih_x = (const float*)d_in[1];
    const float* Whh_x = (const float*)d_in[2];
    const float* bih_x = (const float*)d_in[3];
    const float* bhh_x = (const float*)d_in[4];
    const float* Wih_y = (const float*)d_in[5];
    const float* Whh_y = (const float*)d_in[6];
    const float* bih_y = (const float*)d_in[7];
    const float* bhh_y = (const float*)d_in[8];
    float* out = (float*)d_out;

    prep_kernel<<<1, 256>>>(Wih_x, Wih_y, bih_x, bhh_x, bih_y, bhh_y);
    proj_kernel<0><<<2048, 256>>>(x);                  // pre_x
    scan_kernel<0><<<1024, 128>>>(Whh_x, nullptr);     // scan w -> g_mid [b][w][j][h]
    proj_kernel<1><<<2048, 256>>>(nullptr);            // pre_y
    scan_kernel<1><<<1024, 128>>>(Whh_y, out);         // scan h -> out [b][j][h][w]
}